// round 12
// baseline (speedup 1.0000x reference)
#include <cuda_runtime.h>
#include <stdint.h>
#include <math.h>

// Sizes (fixed for this problem)
#define BB 16
#define LL 128
#define HH 256
#define DD 256
#define BL (BB*LL)              // 2048
#define NEL (BB*LL*LL)          // 262144
#define OFF_MS 0
#define OFF_S  NEL              // 262144
#define OFF_E  (2*NEL)          // 524288
#define OFF_GB (3*NEL)          // 786432
#define OFF_LSM (3*NEL + LL*LL) // 802816
#define OFF_ER (OFF_LSM + 1)    // 802817

// Scratch (no cudaMalloc allowed).
__device__ float g_el[BL*DD];        // exp(2*dot_l)
__device__ float g_er[BL*DD];        // exp(2*dot_r)
__device__ float g_ent_part[1024];
__device__ float g_lsm_part[1024];
__device__ int   g_cnt[LL*LL];       // zero at load; last block resets
__device__ int   g_steal;            // work-steal counter (reset each call)
__device__ int   g_done;             // block completion counter

#define TWO_LOG2E 2.8853900817779268f   // 2*log2(e)

__device__ __forceinline__ float ex2f(float x) {
    float e; asm("ex2.approx.f32 %0, %1;" : "=f"(e) : "f"(x)); return e;
}
__device__ __forceinline__ float rcpf(float x) {
    float r; asm("rcp.approx.f32 %0, %1;" : "=f"(r) : "f"(x)); return r;
}

// ---------------------------------------------------------------------------
// 4xTF32 split helpers (fp32-equivalent accuracy on tensor pipe)
// ---------------------------------------------------------------------------
__device__ __forceinline__ void tf32_split(float x, uint32_t& hi, uint32_t& lo) {
    asm("cvt.rna.tf32.f32 %0, %1;" : "=r"(hi) : "f"(x));
    float l = x - __uint_as_float(hi);
    asm("cvt.rna.tf32.f32 %0, %1;" : "=r"(lo) : "f"(l));
}
__device__ __forceinline__ void split4(float4 v, float4& h, float4& l) {
    uint32_t hh, ll;
    tf32_split(v.x, hh, ll); h.x = __uint_as_float(hh); l.x = __uint_as_float(ll);
    tf32_split(v.y, hh, ll); h.y = __uint_as_float(hh); l.y = __uint_as_float(ll);
    tf32_split(v.z, hh, ll); h.z = __uint_as_float(hh); l.z = __uint_as_float(ll);
    tf32_split(v.w, hh, ll); h.w = __uint_as_float(hh); l.w = __uint_as_float(ll);
}
__device__ __forceinline__ void mma_tf32(float* c, const uint32_t* a,
                                         const uint32_t* b) {
    asm volatile(
        "mma.sync.aligned.m16n8k8.row.col.f32.tf32.tf32.f32 "
        "{%0,%1,%2,%3}, {%4,%5,%6,%7}, {%8,%9}, {%0,%1,%2,%3};"
        : "+f"(c[0]), "+f"(c[1]), "+f"(c[2]), "+f"(c[3])
        : "r"(a[0]), "r"(a[1]), "r"(a[2]), "r"(a[3]), "r"(b[0]), "r"(b[1]));
}

// ---------------------------------------------------------------------------
// GEMM (tensor core): C = exp(2 * (A @ W)), TF32 split done ONCE at STS time.
// Block 256 thr (8 warps), tile 64m x 64n, warp tile 32m x 16n.
// k staged 32/stage, 8 stages; hi/lo staged in separate smem arrays.
// Inner loop is pure LDS + MMA. grid (4, 32, 2) = 256 blocks.
// ---------------------------------------------------------------------------
#define GA_STR 36
#define GB_STR 72

__global__ __launch_bounds__(256, 2)
void gemm_tc_kernel(const float* __restrict__ A,
                    const float* __restrict__ Wl,
                    const float* __restrict__ Wr) {
    const float* W = blockIdx.z ? Wr : Wl;
    float* C = blockIdx.z ? g_er : g_el;
    __shared__ __align__(16) float Ash[64 * GA_STR];
    __shared__ __align__(16) float Asl[64 * GA_STR];
    __shared__ __align__(16) float Bsh[32 * GB_STR];
    __shared__ __align__(16) float Bsl[32 * GB_STR];
    const int tid = threadIdx.x;
    const int w = tid >> 5, lane = tid & 31;
    const int m0 = blockIdx.y * 64, n0 = blockIdx.x * 64;
    const int wm = (w & 1) * 32, wn = (w >> 1) * 16;

    const int arow = tid >> 3, acol = (tid & 7) * 4;   // A: 2x 32rows x 32k
    const int brow = tid >> 4, bcol = (tid & 15) * 4;  // W: 2x 16rows x 64n
    const float* Ap = A + (m0 + arow) * 256 + acol;
    const float* Wp = W + brow * 256 + n0 + bcol;

    float4 ra0 = *(const float4*)(Ap);
    float4 ra1 = *(const float4*)(Ap + 32 * 256);
    float4 rb0 = *(const float4*)(Wp);
    float4 rb1 = *(const float4*)(Wp + 16 * 256);

    float acc[2][2][4];
#pragma unroll
    for (int mi = 0; mi < 2; mi++)
#pragma unroll
        for (int ni = 0; ni < 2; ni++)
#pragma unroll
            for (int q = 0; q < 4; q++) acc[mi][ni][q] = 0.0f;

    const int r = lane >> 2, cq = lane & 3;

    for (int s = 0; s < 8; s++) {
        float4 h, l;
        split4(ra0, h, l);
        *(float4*)&Ash[arow * GA_STR + acol] = h;
        *(float4*)&Asl[arow * GA_STR + acol] = l;
        split4(ra1, h, l);
        *(float4*)&Ash[(arow + 32) * GA_STR + acol] = h;
        *(float4*)&Asl[(arow + 32) * GA_STR + acol] = l;
        split4(rb0, h, l);
        *(float4*)&Bsh[brow * GB_STR + bcol] = h;
        *(float4*)&Bsl[brow * GB_STR + bcol] = l;
        split4(rb1, h, l);
        *(float4*)&Bsh[(brow + 16) * GB_STR + bcol] = h;
        *(float4*)&Bsl[(brow + 16) * GB_STR + bcol] = l;
        __syncthreads();
        if (s < 7) {
            ra0 = *(const float4*)(Ap + (s + 1) * 32);
            ra1 = *(const float4*)(Ap + (s + 1) * 32 + 32 * 256);
            rb0 = *(const float4*)(Wp + (s + 1) * 32 * 256);
            rb1 = *(const float4*)(Wp + (s + 1) * 32 * 256 + 16 * 256);
        }
#pragma unroll
        for (int k8 = 0; k8 < 32; k8 += 8) {
            uint32_t ahi[2][4], alo[2][4];
#pragma unroll
            for (int mi = 0; mi < 2; mi++) {
                const int base = (wm + mi * 16 + r) * GA_STR + k8 + cq;
                ahi[mi][0] = __float_as_uint(Ash[base]);
                ahi[mi][1] = __float_as_uint(Ash[base + 8 * GA_STR]);
                ahi[mi][2] = __float_as_uint(Ash[base + 4]);
                ahi[mi][3] = __float_as_uint(Ash[base + 8 * GA_STR + 4]);
                alo[mi][0] = __float_as_uint(Asl[base]);
                alo[mi][1] = __float_as_uint(Asl[base + 8 * GA_STR]);
                alo[mi][2] = __float_as_uint(Asl[base + 4]);
                alo[mi][3] = __float_as_uint(Asl[base + 8 * GA_STR + 4]);
            }
            uint32_t bhi[2][2], blo[2][2];
#pragma unroll
            for (int ni = 0; ni < 2; ni++) {
                const int base = (k8 + cq) * GB_STR + wn + ni * 8 + r;
                bhi[ni][0] = __float_as_uint(Bsh[base]);
                bhi[ni][1] = __float_as_uint(Bsh[base + 4 * GB_STR]);
                blo[ni][0] = __float_as_uint(Bsl[base]);
                blo[ni][1] = __float_as_uint(Bsl[base + 4 * GB_STR]);
            }
#pragma unroll
            for (int mi = 0; mi < 2; mi++)
#pragma unroll
                for (int ni = 0; ni < 2; ni++) {
                    mma_tf32(acc[mi][ni], alo[mi], blo[ni]);
                    mma_tf32(acc[mi][ni], alo[mi], bhi[ni]);
                    mma_tf32(acc[mi][ni], ahi[mi], blo[ni]);
                    mma_tf32(acc[mi][ni], ahi[mi], bhi[ni]);
                }
        }
        __syncthreads();
    }

#pragma unroll
    for (int mi = 0; mi < 2; mi++)
#pragma unroll
        for (int ni = 0; ni < 2; ni++) {
            int row = m0 + wm + mi * 16 + r;
            int col = n0 + wn + ni * 8 + 2 * cq;
            float2 lo2, hi2;
            lo2.x = ex2f(acc[mi][ni][0] * TWO_LOG2E);
            lo2.y = ex2f(acc[mi][ni][1] * TWO_LOG2E);
            hi2.x = ex2f(acc[mi][ni][2] * TWO_LOG2E);
            hi2.y = ex2f(acc[mi][ni][3] * TWO_LOG2E);
            *(float2*)&C[row * 256 + col]       = lo2;
            *(float2*)&C[(row + 8) * 256 + col] = hi2;
        }
}

// ---------------------------------------------------------------------------
// Threefry-2x32, key = (0,1) [jax.random.key(1)], partitionable bits.
// ---------------------------------------------------------------------------
__device__ __forceinline__ uint32_t rotl32(uint32_t v, int r) {
    return __funnelshift_l(v, v, r);
}
__device__ __forceinline__ uint32_t threefry_bits(uint32_t idx) {
    const uint32_t K0 = 0u, K1 = 1u, K2 = 0x1BD11BDBu;
    uint32_t x0 = K0;
    uint32_t x1 = idx + K1;
#define TF_ROUND(r) { x0 += x1; x1 = rotl32(x1, (r)); x1 ^= x0; }
    TF_ROUND(13) TF_ROUND(15) TF_ROUND(26) TF_ROUND(6)
    x0 += K1; x1 += K2 + 1u;
    TF_ROUND(17) TF_ROUND(29) TF_ROUND(16) TF_ROUND(24)
    x0 += K2; x1 += K0 + 2u;
    TF_ROUND(13) TF_ROUND(15) TF_ROUND(26) TF_ROUND(6)
    x0 += K0; x1 += K1 + 3u;
    TF_ROUND(17) TF_ROUND(29) TF_ROUND(16) TF_ROUND(24)
    x0 += K1; x1 += K2 + 4u;
    TF_ROUND(13) TF_ROUND(15) TF_ROUND(26) TF_ROUND(6)
    x0 += K2; x1 += K0 + 5u;
#undef TF_ROUND
    return x0 ^ x1;
}

// Epilogue for one (b,i,j): writes ms/sample/entropy, counts sample into
// g_cnt (integer atomic -> deterministic), returns (entropy, lsm_term).
__device__ __forceinline__ float2 epi_one(int b, int i, int j, float logit,
                                          float* __restrict__ out) {
    float ms = (i == j) ? (logit - 1e8f) : logit;
    uint32_t f = ((uint32_t)b << 14) | ((uint32_t)i << 7) | (uint32_t)j;
    uint32_t bits = threefry_bits(f);
    float u = __uint_as_float((bits >> 9) | 0x3f800000u) - 1.0f;
    float p = 1.0f / (1.0f + expf(-ms));
    float c = log1pf(expf(-fabsf(ms)));          // shared softplus tail
    float sp_pos = fmaxf(ms, 0.0f) + c;          // softplus(ms)
    float sp_neg = fmaxf(-ms, 0.0f) + c;         // softplus(-ms)
    float ent = fmaf(p, sp_neg, (1.0f - p) * sp_pos);
    float s;
    if (u < p) { s = 1.0f; atomicAdd(&g_cnt[i * LL + j], 1); } else s = 0.0f;
    out[OFF_MS + f] = ms;
    out[OFF_S + f]  = s;
    out[OFF_E + f]  = ent;
    float lsm = sp_pos - ms * s;
    return make_float2(ent, lsm);
}

// ---------------------------------------------------------------------------
// Pairwise core with WARP-LEVEL WORK STEALING + fused tail.
// 1024 tiles of 16(i) x 16(j); each warp steals tiles off g_steal.
// Per warp: own smem buffer (32 rows x 68, d-chunk 64), 2x4 microtile
// (i = ti + {0,8}, j = tj + {0,4,8,12}) -> 3.5 B LDS per element-d,
// conflict-free (row banks 4*ti / 4*(tj+4q)+... all distinct per access).
// Last finishing block does graph_batch conversion + final reductions.
// ---------------------------------------------------------------------------
#define PWC 68

__global__ __launch_bounds__(128, 4)
void pairwise_kernel(const float* __restrict__ Uv,
                     const float* __restrict__ biasp,
                     float* __restrict__ out) {
    __shared__ __align__(16) float sbuf[4][32 * PWC];
    __shared__ __align__(16) float su[256];
    __shared__ int s_last;
    const int tid = threadIdx.x;
    const int wid = tid >> 5, lane = tid & 31;
    const int ti = lane & 7, tj = lane >> 3;   // ti: 0..7 (i), tj: 0..3 (j)
    su[tid] = Uv[tid];
    su[tid + 128] = Uv[tid + 128];
    __syncthreads();
    const float bias = __ldg(biasp);
    float* sw = sbuf[wid];

    for (;;) {
        int t;
        if (lane == 0) t = atomicAdd(&g_steal, 1);
        t = __shfl_sync(0xffffffffu, t, 0);
        if (t >= 1024) break;
        const int b = t >> 6, it = (t >> 3) & 7, jt = t & 7;
        const int ibase = it * 16, jbase = jt * 16;

        float acc[2][4];
#pragma unroll
        for (int u = 0; u < 2; u++)
#pragma unroll
            for (int v = 0; v < 4; v++) acc[u][v] = 0.0f;

        for (int k0 = 0; k0 < 256; k0 += 64) {
            __syncwarp();
            // load 16 L rows + 16 R rows x 64 floats (16 float4 per row)
#pragma unroll
            for (int ii = 0; ii < 16; ii++) {
                int idx = ii * 32 + lane;          // 0..511
                int rr = idx >> 4, cc = (idx & 15) * 4;
                const float* src = (rr < 16)
                    ? &g_el[(b * 128 + ibase + rr) * 256 + k0 + cc]
                    : &g_er[(b * 128 + jbase + (rr - 16)) * 256 + k0 + cc];
                *(float4*)&sw[rr * PWC + cc] = *(const float4*)src;
            }
            __syncwarp();
            const float* pl0 = sw + ti * PWC;
            const float* pl1 = sw + (ti + 8) * PWC;
            const float* pr0 = sw + (16 + tj) * PWC;
            const float* pr1 = sw + (16 + tj + 4) * PWC;
            const float* pr2 = sw + (16 + tj + 8) * PWC;
            const float* pr3 = sw + (16 + tj + 12) * PWC;
            const float* pu  = su + k0;
#pragma unroll 2
            for (int d = 0; d < 64; d += 4) {
                float4 L0 = *(const float4*)(pl0 + d);
                float4 L1 = *(const float4*)(pl1 + d);
                float4 R0 = *(const float4*)(pr0 + d);
                float4 R1 = *(const float4*)(pr1 + d);
                float4 R2 = *(const float4*)(pr2 + d);
                float4 R3 = *(const float4*)(pr3 + d);
                float4 U  = *(const float4*)(pu + d);
#define PWB(CMP)                                                              \
                {                                                             \
                    float uu = U.CMP;                                         \
                    acc[0][0] = fmaf(uu, rcpf(fmaf(L0.CMP, R0.CMP, 1.0f)) - 0.5f, acc[0][0]); \
                    acc[0][1] = fmaf(uu, rcpf(fmaf(L0.CMP, R1.CMP, 1.0f)) - 0.5f, acc[0][1]); \
                    acc[0][2] = fmaf(uu, rcpf(fmaf(L0.CMP, R2.CMP, 1.0f)) - 0.5f, acc[0][2]); \
                    acc[0][3] = fmaf(uu, rcpf(fmaf(L0.CMP, R3.CMP, 1.0f)) - 0.5f, acc[0][3]); \
                    acc[1][0] = fmaf(uu, rcpf(fmaf(L1.CMP, R0.CMP, 1.0f)) - 0.5f, acc[1][0]); \
                    acc[1][1] = fmaf(uu, rcpf(fmaf(L1.CMP, R1.CMP, 1.0f)) - 0.5f, acc[1][1]); \
                    acc[1][2] = fmaf(uu, rcpf(fmaf(L1.CMP, R2.CMP, 1.0f)) - 0.5f, acc[1][2]); \
                    acc[1][3] = fmaf(uu, rcpf(fmaf(L1.CMP, R3.CMP, 1.0f)) - 0.5f, acc[1][3]); \
                }
                PWB(x) PWB(y) PWB(z) PWB(w)
#undef PWB
            }
        }

        float ent = 0.0f, lsm = 0.0f;
#pragma unroll
        for (int u = 0; u < 2; u++)
#pragma unroll
            for (int v = 0; v < 4; v++) {
                float2 e = epi_one(b, ibase + ti + 8 * u, jbase + tj + 4 * v,
                                   fmaf(-2.0f, acc[u][v], bias), out);
                ent += e.x; lsm += e.y;
            }
        // warp reduce (deterministic) -> per-tile partials
#pragma unroll
        for (int o = 16; o > 0; o >>= 1) {
            ent += __shfl_xor_sync(0xffffffffu, ent, o);
            lsm += __shfl_xor_sync(0xffffffffu, lsm, o);
        }
        if (lane == 0) { g_ent_part[t] = ent; g_lsm_part[t] = lsm; }
    }

    // ---- fused tail: last block finishes ----
    __syncthreads();
    if (tid == 0) {
        __threadfence();
        int d = atomicAdd(&g_done, 1);
        s_last = (d == (int)gridDim.x - 1) ? 1 : 0;
    }
    __syncthreads();
    if (s_last) {
        __threadfence();
        // graph_batch: 16384 elements / 128 threads
        for (int k = tid; k < LL * LL; k += 128) {
            out[OFF_GB + k] = (float)g_cnt[k] * 0.0625f;
            g_cnt[k] = 0;
        }
        if (tid < 16) {   // entropy_regularization: 64 tile-partials per batch
            float s = 0.0f;
#pragma unroll
            for (int k = 0; k < 64; k++) s += g_ent_part[tid * 64 + k];
            out[OFF_ER + tid] = s * (1.0f / 16384.0f);
        }
        if (tid >= 32 && tid < 64) {   // log_softmax: 1024 partials
            int ln = tid - 32;
            float s = 0.0f;
#pragma unroll
            for (int k = 0; k < 32; k++) s += g_lsm_part[ln * 32 + k];
#pragma unroll
            for (int o = 16; o > 0; o >>= 1)
                s += __shfl_xor_sync(0xffffffffu, s, o);
            if (ln == 0) out[OFF_LSM] = s * (1.0f / (float)NEL);
        }
        if (tid == 64) { g_steal = 0; g_done = 0; }  // reset for graph replay
    }
}

// ---------------------------------------------------------------------------
extern "C" void kernel_launch(void* const* d_in, const int* in_sizes, int n_in,
                              void* d_out, int out_size) {
    (void)in_sizes; (void)n_in; (void)out_size;
    const float* enc  = (const float*)d_in[0]; // (16,128,256)
    const float* W_l  = (const float*)d_in[1]; // (256,256)
    const float* W_r  = (const float*)d_in[2]; // (256,256)
    const float* U    = (const float*)d_in[3]; // (256,)
    const float* bias = (const float*)d_in[4]; // (1,)
    float* out = (float*)d_out;

    gemm_tc_kernel<<<dim3(4, 32, 2), 256>>>(enc, W_l, W_r);
    pairwise_kernel<<<592, 128>>>(U, bias, out);
}

// round 13
// speedup vs baseline: 1.2761x; 1.2761x over previous
#include <cuda_runtime.h>
#include <stdint.h>
#include <math.h>

// Sizes (fixed for this problem)
#define BB 16
#define LL 128
#define HH 256
#define DD 256
#define BL (BB*LL)              // 2048
#define NEL (BB*LL*LL)          // 262144
#define OFF_MS 0
#define OFF_S  NEL              // 262144
#define OFF_E  (2*NEL)          // 524288
#define OFF_GB (3*NEL)          // 786432
#define OFF_LSM (3*NEL + LL*LL) // 802816
#define OFF_ER (OFF_LSM + 1)    // 802817

// Scratch (no cudaMalloc allowed).
__device__ float g_el[BL*DD];        // exp(2*dot_l)
__device__ float g_er[BL*DD];        // exp(2*dot_r)
__device__ float g_ent_part[512];
__device__ float g_lsm_part[512];
__device__ int   g_cnt[LL*LL];       // zero at load; last block resets
__device__ int   g_steal;            // block work-steal counter
__device__ int   g_done;             // block completion counter

#define TWO_LOG2E 2.8853900817779268f   // 2*log2(e)

__device__ __forceinline__ float ex2f(float x) {
    float e; asm("ex2.approx.f32 %0, %1;" : "=f"(e) : "f"(x)); return e;
}
__device__ __forceinline__ float rcpf(float x) {
    float r; asm("rcp.approx.f32 %0, %1;" : "=f"(r) : "f"(x)); return r;
}

// ---------------------------------------------------------------------------
// 4xTF32 split helpers (fp32-equivalent accuracy on tensor pipe)
// ---------------------------------------------------------------------------
__device__ __forceinline__ void tf32_split(float x, uint32_t& hi, uint32_t& lo) {
    asm("cvt.rna.tf32.f32 %0, %1;" : "=r"(hi) : "f"(x));
    float l = x - __uint_as_float(hi);
    asm("cvt.rna.tf32.f32 %0, %1;" : "=r"(lo) : "f"(l));
}
__device__ __forceinline__ void split4(float4 v, float4& h, float4& l) {
    uint32_t hh, ll;
    tf32_split(v.x, hh, ll); h.x = __uint_as_float(hh); l.x = __uint_as_float(ll);
    tf32_split(v.y, hh, ll); h.y = __uint_as_float(hh); l.y = __uint_as_float(ll);
    tf32_split(v.z, hh, ll); h.z = __uint_as_float(hh); l.z = __uint_as_float(ll);
    tf32_split(v.w, hh, ll); h.w = __uint_as_float(hh); l.w = __uint_as_float(ll);
}
__device__ __forceinline__ void mma_tf32(float* c, const uint32_t* a,
                                         const uint32_t* b) {
    asm volatile(
        "mma.sync.aligned.m16n8k8.row.col.f32.tf32.tf32.f32 "
        "{%0,%1,%2,%3}, {%4,%5,%6,%7}, {%8,%9}, {%0,%1,%2,%3};"
        : "+f"(c[0]), "+f"(c[1]), "+f"(c[2]), "+f"(c[3])
        : "r"(a[0]), "r"(a[1]), "r"(a[2]), "r"(a[3]), "r"(b[0]), "r"(b[1]));
}

// ---------------------------------------------------------------------------
// GEMM (tensor core): C = exp(2 * (A @ W)), TF32 split at STS time.
// 128 tiles of 128m x 64n -> grid (4, 16, 2) = 128 blocks, 1 per SM, 1 wave.
// 256 thr / 8 warps; warp tile 32m x 32n (2 m-frags x 4 n-frags m16n8k8).
// k staged 32/stage, 8 stages. Inner loop pure LDS + MMA.
// ---------------------------------------------------------------------------
#define GA_STR 36
#define GB_STR 72

__global__ __launch_bounds__(256, 1)
void gemm_tc_kernel(const float* __restrict__ A,
                    const float* __restrict__ Wl,
                    const float* __restrict__ Wr) {
    const float* W = blockIdx.z ? Wr : Wl;
    float* C = blockIdx.z ? g_er : g_el;
    __shared__ __align__(16) float Ash[128 * GA_STR];
    __shared__ __align__(16) float Asl[128 * GA_STR];
    __shared__ __align__(16) float Bsh[32 * GB_STR];
    __shared__ __align__(16) float Bsl[32 * GB_STR];
    const int tid = threadIdx.x;
    const int w = tid >> 5, lane = tid & 31;
    const int m0 = blockIdx.y * 128, n0 = blockIdx.x * 64;
    const int wm = (w >> 1) * 32, wn = (w & 1) * 32;
    const int r = lane >> 2, cq = lane & 3;

    // global load mapping: A 128 rows x 32 k (4 float4/thr), B 32 x 64 (2/thr)
    int aro[4], aco[4];
#pragma unroll
    for (int q = 0; q < 4; q++) {
        int idx = q * 256 + tid;
        aro[q] = idx >> 3; aco[q] = (idx & 7) * 4;
    }
    int bro[2], bco[2];
#pragma unroll
    for (int q = 0; q < 2; q++) {
        int idx = q * 256 + tid;
        bro[q] = idx >> 4; bco[q] = (idx & 15) * 4;
    }

    float4 ra[4], rb[2];
#pragma unroll
    for (int q = 0; q < 4; q++)
        ra[q] = *(const float4*)&A[(m0 + aro[q]) * 256 + aco[q]];
#pragma unroll
    for (int q = 0; q < 2; q++)
        rb[q] = *(const float4*)&W[bro[q] * 256 + n0 + bco[q]];

    float acc[2][4][4];
#pragma unroll
    for (int mi = 0; mi < 2; mi++)
#pragma unroll
        for (int ni = 0; ni < 4; ni++)
#pragma unroll
            for (int q = 0; q < 4; q++) acc[mi][ni][q] = 0.0f;

    for (int s = 0; s < 8; s++) {
        float4 h, l;
#pragma unroll
        for (int q = 0; q < 4; q++) {
            split4(ra[q], h, l);
            *(float4*)&Ash[aro[q] * GA_STR + aco[q]] = h;
            *(float4*)&Asl[aro[q] * GA_STR + aco[q]] = l;
        }
#pragma unroll
        for (int q = 0; q < 2; q++) {
            split4(rb[q], h, l);
            *(float4*)&Bsh[bro[q] * GB_STR + bco[q]] = h;
            *(float4*)&Bsl[bro[q] * GB_STR + bco[q]] = l;
        }
        __syncthreads();
        if (s < 7) {
#pragma unroll
            for (int q = 0; q < 4; q++)
                ra[q] = *(const float4*)&A[(m0 + aro[q]) * 256 + (s + 1) * 32 + aco[q]];
#pragma unroll
            for (int q = 0; q < 2; q++)
                rb[q] = *(const float4*)&W[((s + 1) * 32 + bro[q]) * 256 + n0 + bco[q]];
        }
#pragma unroll
        for (int k8 = 0; k8 < 32; k8 += 8) {
            uint32_t ahi[2][4], alo[2][4];
#pragma unroll
            for (int mi = 0; mi < 2; mi++) {
                const int base = (wm + mi * 16 + r) * GA_STR + k8 + cq;
                ahi[mi][0] = __float_as_uint(Ash[base]);
                ahi[mi][1] = __float_as_uint(Ash[base + 8 * GA_STR]);
                ahi[mi][2] = __float_as_uint(Ash[base + 4]);
                ahi[mi][3] = __float_as_uint(Ash[base + 8 * GA_STR + 4]);
                alo[mi][0] = __float_as_uint(Asl[base]);
                alo[mi][1] = __float_as_uint(Asl[base + 8 * GA_STR]);
                alo[mi][2] = __float_as_uint(Asl[base + 4]);
                alo[mi][3] = __float_as_uint(Asl[base + 8 * GA_STR + 4]);
            }
            uint32_t bhi[4][2], blo[4][2];
#pragma unroll
            for (int ni = 0; ni < 4; ni++) {
                const int base = (k8 + cq) * GB_STR + wn + ni * 8 + r;
                bhi[ni][0] = __float_as_uint(Bsh[base]);
                bhi[ni][1] = __float_as_uint(Bsh[base + 4 * GB_STR]);
                blo[ni][0] = __float_as_uint(Bsl[base]);
                blo[ni][1] = __float_as_uint(Bsl[base + 4 * GB_STR]);
            }
#pragma unroll
            for (int mi = 0; mi < 2; mi++)
#pragma unroll
                for (int ni = 0; ni < 4; ni++) {
                    mma_tf32(acc[mi][ni], alo[mi], blo[ni]);
                    mma_tf32(acc[mi][ni], alo[mi], bhi[ni]);
                    mma_tf32(acc[mi][ni], ahi[mi], blo[ni]);
                    mma_tf32(acc[mi][ni], ahi[mi], bhi[ni]);
                }
        }
        __syncthreads();
    }

#pragma unroll
    for (int mi = 0; mi < 2; mi++)
#pragma unroll
        for (int ni = 0; ni < 4; ni++) {
            int row = m0 + wm + mi * 16 + r;
            int col = n0 + wn + ni * 8 + 2 * cq;
            float2 lo2, hi2;
            lo2.x = ex2f(acc[mi][ni][0] * TWO_LOG2E);
            lo2.y = ex2f(acc[mi][ni][1] * TWO_LOG2E);
            hi2.x = ex2f(acc[mi][ni][2] * TWO_LOG2E);
            hi2.y = ex2f(acc[mi][ni][3] * TWO_LOG2E);
            *(float2*)&C[row * 256 + col]       = lo2;
            *(float2*)&C[(row + 8) * 256 + col] = hi2;
        }
}

// ---------------------------------------------------------------------------
// Threefry-2x32, key = (0,1) [jax.random.key(1)], partitionable bits.
// ---------------------------------------------------------------------------
__device__ __forceinline__ uint32_t rotl32(uint32_t v, int r) {
    return __funnelshift_l(v, v, r);
}
__device__ __forceinline__ uint32_t threefry_bits(uint32_t idx) {
    const uint32_t K0 = 0u, K1 = 1u, K2 = 0x1BD11BDBu;
    uint32_t x0 = K0;
    uint32_t x1 = idx + K1;
#define TF_ROUND(r) { x0 += x1; x1 = rotl32(x1, (r)); x1 ^= x0; }
    TF_ROUND(13) TF_ROUND(15) TF_ROUND(26) TF_ROUND(6)
    x0 += K1; x1 += K2 + 1u;
    TF_ROUND(17) TF_ROUND(29) TF_ROUND(16) TF_ROUND(24)
    x0 += K2; x1 += K0 + 2u;
    TF_ROUND(13) TF_ROUND(15) TF_ROUND(26) TF_ROUND(6)
    x0 += K0; x1 += K1 + 3u;
    TF_ROUND(17) TF_ROUND(29) TF_ROUND(16) TF_ROUND(24)
    x0 += K1; x1 += K2 + 4u;
    TF_ROUND(13) TF_ROUND(15) TF_ROUND(26) TF_ROUND(6)
    x0 += K2; x1 += K0 + 5u;
#undef TF_ROUND
    return x0 ^ x1;
}

// Epilogue for one (b,i,j): writes ms/sample/entropy, counts sample into
// g_cnt (integer atomic -> deterministic), returns (entropy, lsm_term).
__device__ __forceinline__ float2 epi_one(int b, int i, int j, float logit,
                                          float* __restrict__ out) {
    float ms = (i == j) ? (logit - 1e8f) : logit;
    uint32_t f = ((uint32_t)b << 14) | ((uint32_t)i << 7) | (uint32_t)j;
    uint32_t bits = threefry_bits(f);
    float u = __uint_as_float((bits >> 9) | 0x3f800000u) - 1.0f;
    float p = 1.0f / (1.0f + expf(-ms));
    float c = log1pf(expf(-fabsf(ms)));          // shared softplus tail
    float sp_pos = fmaxf(ms, 0.0f) + c;          // softplus(ms)
    float sp_neg = fmaxf(-ms, 0.0f) + c;         // softplus(-ms)
    float ent = fmaf(p, sp_neg, (1.0f - p) * sp_pos);
    float s;
    if (u < p) { s = 1.0f; atomicAdd(&g_cnt[i * LL + j], 1); } else s = 0.0f;
    out[OFF_MS + f] = ms;
    out[OFF_S + f]  = s;
    out[OFF_E + f]  = ent;
    float lsm = sp_pos - ms * s;
    return make_float2(ent, lsm);
}

// ---------------------------------------------------------------------------
// Pairwise core: BLOCK-level work stealing + fused tail.
// 296 blocks x 128 thr (= exactly 2 resident/SM, one wave).
// 512 tiles of 16(i) x 32(j): t -> b = t>>5, it = (t>>2)&7, jt = t&3.
// 2x2 microtile: i = ti+{0,8} (ti=tid&7), j = tj+{0,16} (tj=tid>>3, 0..15).
// 4 B LDS per element-d -> MUFU (rcp) is the only binding pipe (~15.5us/chip).
// Last finishing block converts graph_batch + final reductions + resets.
// ---------------------------------------------------------------------------
#define PW_STR 260

__global__ __launch_bounds__(128, 2)
void pairwise_kernel(const float* __restrict__ Uv,
                     const float* __restrict__ biasp,
                     float* __restrict__ out) {
    __shared__ __align__(16) float sl[16 * PW_STR];
    __shared__ __align__(16) float sr[32 * PW_STR];
    __shared__ __align__(16) float su[256];
    __shared__ float rshare[2][4];
    __shared__ int s_t;
    __shared__ int s_last;
    const int tid = threadIdx.x;
    const int lane = tid & 31, wid = tid >> 5;
    const int ti = tid & 7, tj = tid >> 3;   // i-base (0..7), j-base (0..15)
    su[tid] = Uv[tid];
    su[tid + 128] = Uv[tid + 128];
    const float bias = __ldg(biasp);

    for (;;) {
        __syncthreads();            // protect smem + s_t reuse
        if (tid == 0) s_t = atomicAdd(&g_steal, 1);
        __syncthreads();
        const int t = s_t;
        if (t >= 512) break;
        const int b = t >> 5, it = (t >> 2) & 7, jt = t & 3;
        const int ibase = it * 16, jbase = jt * 32;

        // load 16 L rows + 32 R rows x 256 floats (64 float4 per row)
#pragma unroll
        for (int q = 0; q < 24; q++) {
            int idx = q * 128 + tid;           // 0..3071
            int rr = idx >> 6, cc = (idx & 63) * 4;
            if (rr < 16) {
                *(float4*)&sl[rr * PW_STR + cc] =
                    *(const float4*)&g_el[(b * 128 + ibase + rr) * 256 + cc];
            } else {
                *(float4*)&sr[(rr - 16) * PW_STR + cc] =
                    *(const float4*)&g_er[(b * 128 + jbase + (rr - 16)) * 256 + cc];
            }
        }
        __syncthreads();

        const float* pl0 = sl + ti * PW_STR;
        const float* pl1 = sl + (ti + 8) * PW_STR;
        const float* pr0 = sr + tj * PW_STR;
        const float* pr1 = sr + (tj + 16) * PW_STR;
        float a00 = 0.f, a01 = 0.f, a10 = 0.f, a11 = 0.f;
#pragma unroll 4
        for (int d = 0; d < 256; d += 4) {
            float4 L0 = *(const float4*)(pl0 + d);
            float4 L1 = *(const float4*)(pl1 + d);
            float4 R0 = *(const float4*)(pr0 + d);
            float4 R1 = *(const float4*)(pr1 + d);
            float4 U  = *(const float4*)(su + d);
            a00 = fmaf(U.x, rcpf(fmaf(L0.x, R0.x, 1.0f)) - 0.5f, a00);
            a01 = fmaf(U.x, rcpf(fmaf(L0.x, R1.x, 1.0f)) - 0.5f, a01);
            a10 = fmaf(U.x, rcpf(fmaf(L1.x, R0.x, 1.0f)) - 0.5f, a10);
            a11 = fmaf(U.x, rcpf(fmaf(L1.x, R1.x, 1.0f)) - 0.5f, a11);
            a00 = fmaf(U.y, rcpf(fmaf(L0.y, R0.y, 1.0f)) - 0.5f, a00);
            a01 = fmaf(U.y, rcpf(fmaf(L0.y, R1.y, 1.0f)) - 0.5f, a01);
            a10 = fmaf(U.y, rcpf(fmaf(L1.y, R0.y, 1.0f)) - 0.5f, a10);
            a11 = fmaf(U.y, rcpf(fmaf(L1.y, R1.y, 1.0f)) - 0.5f, a11);
            a00 = fmaf(U.z, rcpf(fmaf(L0.z, R0.z, 1.0f)) - 0.5f, a00);
            a01 = fmaf(U.z, rcpf(fmaf(L0.z, R1.z, 1.0f)) - 0.5f, a01);
            a10 = fmaf(U.z, rcpf(fmaf(L1.z, R0.z, 1.0f)) - 0.5f, a10);
            a11 = fmaf(U.z, rcpf(fmaf(L1.z, R1.z, 1.0f)) - 0.5f, a11);
            a00 = fmaf(U.w, rcpf(fmaf(L0.w, R0.w, 1.0f)) - 0.5f, a00);
            a01 = fmaf(U.w, rcpf(fmaf(L0.w, R1.w, 1.0f)) - 0.5f, a01);
            a10 = fmaf(U.w, rcpf(fmaf(L1.w, R0.w, 1.0f)) - 0.5f, a10);
            a11 = fmaf(U.w, rcpf(fmaf(L1.w, R1.w, 1.0f)) - 0.5f, a11);
        }

        float2 e00 = epi_one(b, ibase + ti,     jbase + tj,      fmaf(-2.f, a00, bias), out);
        float2 e01 = epi_one(b, ibase + ti,     jbase + tj + 16, fmaf(-2.f, a01, bias), out);
        float2 e10 = epi_one(b, ibase + ti + 8, jbase + tj,      fmaf(-2.f, a10, bias), out);
        float2 e11 = epi_one(b, ibase + ti + 8, jbase + tj + 16, fmaf(-2.f, a11, bias), out);

        float ent = (e00.x + e01.x) + (e10.x + e11.x);
        float lsm = (e00.y + e01.y) + (e10.y + e11.y);
#pragma unroll
        for (int o = 16; o > 0; o >>= 1) {
            ent += __shfl_xor_sync(0xffffffffu, ent, o);
            lsm += __shfl_xor_sync(0xffffffffu, lsm, o);
        }
        if (lane == 0) { rshare[0][wid] = ent; rshare[1][wid] = lsm; }
        __syncthreads();
        if (tid == 0) {
            float se = 0.f, sm = 0.f;
#pragma unroll
            for (int ww = 0; ww < 4; ww++) { se += rshare[0][ww]; sm += rshare[1][ww]; }
            g_ent_part[t] = se;
            g_lsm_part[t] = sm;
        }
    }

    // ---- fused tail: last finishing block ----
    if (tid == 0) {
        __threadfence();
        int d = atomicAdd(&g_done, 1);
        s_last = (d == (int)gridDim.x - 1) ? 1 : 0;
    }
    __syncthreads();
    if (s_last) {
        __threadfence();
        for (int k = tid; k < LL * LL; k += 128) {
            out[OFF_GB + k] = (float)g_cnt[k] * 0.0625f;
            g_cnt[k] = 0;
        }
        if (tid < 16) {   // entropy_reg: 32 tile-partials per batch, in order
            float s = 0.0f;
#pragma unroll
            for (int k = 0; k < 32; k++) s += g_ent_part[tid * 32 + k];
            out[OFF_ER + tid] = s * (1.0f / 16384.0f);
        }
        if (tid >= 32 && tid < 64) {   // log_softmax: 512 partials
            int ln = tid - 32;
            float s = 0.0f;
#pragma unroll
            for (int k = 0; k < 16; k++) s += g_lsm_part[ln * 16 + k];
#pragma unroll
            for (int o = 16; o > 0; o >>= 1)
                s += __shfl_xor_sync(0xffffffffu, s, o);
            if (ln == 0) out[OFF_LSM] = s * (1.0f / (float)NEL);
        }
        if (tid == 64) { g_steal = 0; g_done = 0; }  // reset for graph replay
    }
}

// ---------------------------------------------------------------------------
extern "C" void kernel_launch(void* const* d_in, const int* in_sizes, int n_in,
                              void* d_out, int out_size) {
    (void)in_sizes; (void)n_in; (void)out_size;
    const float* enc  = (const float*)d_in[0]; // (16,128,256)
    const float* W_l  = (const float*)d_in[1]; // (256,256)
    const float* W_r  = (const float*)d_in[2]; // (256,256)
    const float* U    = (const float*)d_in[3]; // (256,)
    const float* bias = (const float*)d_in[4]; // (1,)
    float* out = (float*)d_out;

    gemm_tc_kernel<<<dim3(4, 16, 2), 256>>>(enc, W_l, W_r);
    pairwise_kernel<<<296, 128>>>(U, bias, out);
}

// round 14
// speedup vs baseline: 1.2923x; 1.0127x over previous
#include <cuda_runtime.h>
#include <stdint.h>
#include <math.h>

// Sizes (fixed for this problem)
#define BB 16
#define LL 128
#define HH 256
#define DD 256
#define BL (BB*LL)              // 2048
#define NEL (BB*LL*LL)          // 262144
#define OFF_MS 0
#define OFF_S  NEL              // 262144
#define OFF_E  (2*NEL)          // 524288
#define OFF_GB (3*NEL)          // 786432
#define OFF_LSM (3*NEL + LL*LL) // 802816
#define OFF_ER (OFF_LSM + 1)    // 802817

// Scratch (no cudaMalloc allowed).
__device__ float g_el[BL*DD];        // exp(2*dot_l)
__device__ float g_er[BL*DD];        // exp(2*dot_r)
__device__ float g_ent_part[512];
__device__ float g_lsm_part[512];
__device__ int   g_cnt[LL*LL];       // zero at load; last block resets
__device__ int   g_done;             // block completion counter

#define TWO_LOG2E 2.8853900817779268f   // 2*log2(e)

__device__ __forceinline__ float ex2f(float x) {
    float e; asm("ex2.approx.f32 %0, %1;" : "=f"(e) : "f"(x)); return e;
}
__device__ __forceinline__ float rcpf(float x) {
    float r; asm("rcp.approx.f32 %0, %1;" : "=f"(r) : "f"(x)); return r;
}

// ---------------------------------------------------------------------------
// 4xTF32 split helpers (fp32-equivalent accuracy on tensor pipe)
// ---------------------------------------------------------------------------
__device__ __forceinline__ void tf32_split(float x, uint32_t& hi, uint32_t& lo) {
    asm("cvt.rna.tf32.f32 %0, %1;" : "=r"(hi) : "f"(x));
    float l = x - __uint_as_float(hi);
    asm("cvt.rna.tf32.f32 %0, %1;" : "=r"(lo) : "f"(l));
}
__device__ __forceinline__ void split4(float4 v, float4& h, float4& l) {
    uint32_t hh, ll;
    tf32_split(v.x, hh, ll); h.x = __uint_as_float(hh); l.x = __uint_as_float(ll);
    tf32_split(v.y, hh, ll); h.y = __uint_as_float(hh); l.y = __uint_as_float(ll);
    tf32_split(v.z, hh, ll); h.z = __uint_as_float(hh); l.z = __uint_as_float(ll);
    tf32_split(v.w, hh, ll); h.w = __uint_as_float(hh); l.w = __uint_as_float(ll);
}
__device__ __forceinline__ void mma_tf32(float* c, const uint32_t* a,
                                         const uint32_t* b) {
    asm volatile(
        "mma.sync.aligned.m16n8k8.row.col.f32.tf32.tf32.f32 "
        "{%0,%1,%2,%3}, {%4,%5,%6,%7}, {%8,%9}, {%0,%1,%2,%3};"
        : "+f"(c[0]), "+f"(c[1]), "+f"(c[2]), "+f"(c[3])
        : "r"(a[0]), "r"(a[1]), "r"(a[2]), "r"(a[3]), "r"(b[0]), "r"(b[1]));
}

// ---------------------------------------------------------------------------
// GEMM (tensor core): C = exp(2 * (A @ W)), TF32 split at STS time.
// 128 tiles of 128m x 64n -> grid (4, 16, 2) = 128 blocks, 1 per SM, 1 wave.
// 256 thr / 8 warps; warp tile 32m x 32n (2 m-frags x 4 n-frags m16n8k8).
// k staged 32/stage, 8 stages. Inner loop pure LDS + MMA. (unchanged vs R13)
// ---------------------------------------------------------------------------
#define GA_STR 36
#define GB_STR 72

__global__ __launch_bounds__(256, 1)
void gemm_tc_kernel(const float* __restrict__ A,
                    const float* __restrict__ Wl,
                    const float* __restrict__ Wr) {
    const float* W = blockIdx.z ? Wr : Wl;
    float* C = blockIdx.z ? g_er : g_el;
    __shared__ __align__(16) float Ash[128 * GA_STR];
    __shared__ __align__(16) float Asl[128 * GA_STR];
    __shared__ __align__(16) float Bsh[32 * GB_STR];
    __shared__ __align__(16) float Bsl[32 * GB_STR];
    const int tid = threadIdx.x;
    const int w = tid >> 5, lane = tid & 31;
    const int m0 = blockIdx.y * 128, n0 = blockIdx.x * 64;
    const int wm = (w >> 1) * 32, wn = (w & 1) * 32;
    const int r = lane >> 2, cq = lane & 3;

    int aro[4], aco[4];
#pragma unroll
    for (int q = 0; q < 4; q++) {
        int idx = q * 256 + tid;
        aro[q] = idx >> 3; aco[q] = (idx & 7) * 4;
    }
    int bro[2], bco[2];
#pragma unroll
    for (int q = 0; q < 2; q++) {
        int idx = q * 256 + tid;
        bro[q] = idx >> 4; bco[q] = (idx & 15) * 4;
    }

    float4 ra[4], rb[2];
#pragma unroll
    for (int q = 0; q < 4; q++)
        ra[q] = *(const float4*)&A[(m0 + aro[q]) * 256 + aco[q]];
#pragma unroll
    for (int q = 0; q < 2; q++)
        rb[q] = *(const float4*)&W[bro[q] * 256 + n0 + bco[q]];

    float acc[2][4][4];
#pragma unroll
    for (int mi = 0; mi < 2; mi++)
#pragma unroll
        for (int ni = 0; ni < 4; ni++)
#pragma unroll
            for (int q = 0; q < 4; q++) acc[mi][ni][q] = 0.0f;

    for (int s = 0; s < 8; s++) {
        float4 h, l;
#pragma unroll
        for (int q = 0; q < 4; q++) {
            split4(ra[q], h, l);
            *(float4*)&Ash[aro[q] * GA_STR + aco[q]] = h;
            *(float4*)&Asl[aro[q] * GA_STR + aco[q]] = l;
        }
#pragma unroll
        for (int q = 0; q < 2; q++) {
            split4(rb[q], h, l);
            *(float4*)&Bsh[bro[q] * GB_STR + bco[q]] = h;
            *(float4*)&Bsl[bro[q] * GB_STR + bco[q]] = l;
        }
        __syncthreads();
        if (s < 7) {
#pragma unroll
            for (int q = 0; q < 4; q++)
                ra[q] = *(const float4*)&A[(m0 + aro[q]) * 256 + (s + 1) * 32 + aco[q]];
#pragma unroll
            for (int q = 0; q < 2; q++)
                rb[q] = *(const float4*)&W[((s + 1) * 32 + bro[q]) * 256 + n0 + bco[q]];
        }
#pragma unroll
        for (int k8 = 0; k8 < 32; k8 += 8) {
            uint32_t ahi[2][4], alo[2][4];
#pragma unroll
            for (int mi = 0; mi < 2; mi++) {
                const int base = (wm + mi * 16 + r) * GA_STR + k8 + cq;
                ahi[mi][0] = __float_as_uint(Ash[base]);
                ahi[mi][1] = __float_as_uint(Ash[base + 8 * GA_STR]);
                ahi[mi][2] = __float_as_uint(Ash[base + 4]);
                ahi[mi][3] = __float_as_uint(Ash[base + 8 * GA_STR + 4]);
                alo[mi][0] = __float_as_uint(Asl[base]);
                alo[mi][1] = __float_as_uint(Asl[base + 8 * GA_STR]);
                alo[mi][2] = __float_as_uint(Asl[base + 4]);
                alo[mi][3] = __float_as_uint(Asl[base + 8 * GA_STR + 4]);
            }
            uint32_t bhi[4][2], blo[4][2];
#pragma unroll
            for (int ni = 0; ni < 4; ni++) {
                const int base = (k8 + cq) * GB_STR + wn + ni * 8 + r;
                bhi[ni][0] = __float_as_uint(Bsh[base]);
                bhi[ni][1] = __float_as_uint(Bsh[base + 4 * GB_STR]);
                blo[ni][0] = __float_as_uint(Bsl[base]);
                blo[ni][1] = __float_as_uint(Bsl[base + 4 * GB_STR]);
            }
#pragma unroll
            for (int mi = 0; mi < 2; mi++)
#pragma unroll
                for (int ni = 0; ni < 4; ni++) {
                    mma_tf32(acc[mi][ni], alo[mi], blo[ni]);
                    mma_tf32(acc[mi][ni], alo[mi], bhi[ni]);
                    mma_tf32(acc[mi][ni], ahi[mi], blo[ni]);
                    mma_tf32(acc[mi][ni], ahi[mi], bhi[ni]);
                }
        }
        __syncthreads();
    }

#pragma unroll
    for (int mi = 0; mi < 2; mi++)
#pragma unroll
        for (int ni = 0; ni < 4; ni++) {
            int row = m0 + wm + mi * 16 + r;
            int col = n0 + wn + ni * 8 + 2 * cq;
            float2 lo2, hi2;
            lo2.x = ex2f(acc[mi][ni][0] * TWO_LOG2E);
            lo2.y = ex2f(acc[mi][ni][1] * TWO_LOG2E);
            hi2.x = ex2f(acc[mi][ni][2] * TWO_LOG2E);
            hi2.y = ex2f(acc[mi][ni][3] * TWO_LOG2E);
            *(float2*)&C[row * 256 + col]       = lo2;
            *(float2*)&C[(row + 8) * 256 + col] = hi2;
        }
}

// ---------------------------------------------------------------------------
// Threefry-2x32, key = (0,1) [jax.random.key(1)], partitionable bits.
// ---------------------------------------------------------------------------
__device__ __forceinline__ uint32_t rotl32(uint32_t v, int r) {
    return __funnelshift_l(v, v, r);
}
__device__ __forceinline__ uint32_t threefry_bits(uint32_t idx) {
    const uint32_t K0 = 0u, K1 = 1u, K2 = 0x1BD11BDBu;
    uint32_t x0 = K0;
    uint32_t x1 = idx + K1;
#define TF_ROUND(r) { x0 += x1; x1 = rotl32(x1, (r)); x1 ^= x0; }
    TF_ROUND(13) TF_ROUND(15) TF_ROUND(26) TF_ROUND(6)
    x0 += K1; x1 += K2 + 1u;
    TF_ROUND(17) TF_ROUND(29) TF_ROUND(16) TF_ROUND(24)
    x0 += K2; x1 += K0 + 2u;
    TF_ROUND(13) TF_ROUND(15) TF_ROUND(26) TF_ROUND(6)
    x0 += K0; x1 += K1 + 3u;
    TF_ROUND(17) TF_ROUND(29) TF_ROUND(16) TF_ROUND(24)
    x0 += K1; x1 += K2 + 4u;
    TF_ROUND(13) TF_ROUND(15) TF_ROUND(26) TF_ROUND(6)
    x0 += K2; x1 += K0 + 5u;
#undef TF_ROUND
    return x0 ^ x1;
}

// Epilogue for one (b,i,j): writes ms/sample/entropy, counts sample into
// g_cnt (integer atomic -> deterministic), returns (entropy, lsm_term).
__device__ __forceinline__ float2 epi_one(int b, int i, int j, float logit,
                                          float* __restrict__ out) {
    float ms = (i == j) ? (logit - 1e8f) : logit;
    uint32_t f = ((uint32_t)b << 14) | ((uint32_t)i << 7) | (uint32_t)j;
    uint32_t bits = threefry_bits(f);
    float u = __uint_as_float((bits >> 9) | 0x3f800000u) - 1.0f;
    float p = 1.0f / (1.0f + expf(-ms));
    float c = log1pf(expf(-fabsf(ms)));          // shared softplus tail
    float sp_pos = fmaxf(ms, 0.0f) + c;          // softplus(ms)
    float sp_neg = fmaxf(-ms, 0.0f) + c;         // softplus(-ms)
    float ent = fmaf(p, sp_neg, (1.0f - p) * sp_pos);
    float s;
    if (u < p) { s = 1.0f; atomicAdd(&g_cnt[i * LL + j], 1); } else s = 0.0f;
    out[OFF_MS + f] = ms;
    out[OFF_S + f]  = s;
    out[OFF_E + f]  = ent;
    float lsm = sp_pos - ms * s;
    return make_float2(ent, lsm);
}

// ---------------------------------------------------------------------------
// Pairwise core (R6-proven shape + 2x2 microtile) + fused tail.
// grid (4, 8, 16): x = j-tile(32), y = i-tile(16), z = batch. 512 blocks,
// 128 thr, __launch_bounds__(128,4): 51KB smem -> 4 blocks/SM, 16 warps/SM.
// Microtile 2x2: i = ti+{0,8} (ti = tid&7), j = tj+{0,16} (tj = tid>>3).
// 5 B LDS per element-d (smem ~10us) < MUFU floor (~16us) -> MUFU-bound.
// Full D=256 resident, conflict-free (stride 260; broadcast groups).
// ---------------------------------------------------------------------------
#define PW_STR 260

__global__ __launch_bounds__(128, 4)
void pairwise_kernel(const float* __restrict__ Uv,
                     const float* __restrict__ biasp,
                     float* __restrict__ out) {
    __shared__ __align__(16) float sl[16 * PW_STR];
    __shared__ __align__(16) float sr[32 * PW_STR];
    __shared__ __align__(16) float su[256];
    __shared__ float rshare[2][4];
    __shared__ int s_last;
    const int tid = threadIdx.x;
    const int lane = tid & 31, wid = tid >> 5;
    const int ti = tid & 7, tj = tid >> 3;    // i-base (0..7), j-base (0..15)
    const int b = blockIdx.z;
    const int ibase = blockIdx.y * 16, jbase = blockIdx.x * 32;

    su[tid] = Uv[tid];
    su[tid + 128] = Uv[tid + 128];

    // load 16 L rows + 32 R rows x 256 floats (64 float4 per row), coalesced
    for (int q = 0; q < 24; q++) {
        int idx = q * 128 + tid;               // 0..3071
        int rr = idx >> 6, cc = (idx & 63) * 4;
        if (rr < 16) {
            *(float4*)&sl[rr * PW_STR + cc] =
                *(const float4*)&g_el[(b * 128 + ibase + rr) * 256 + cc];
        } else {
            *(float4*)&sr[(rr - 16) * PW_STR + cc] =
                *(const float4*)&g_er[(b * 128 + jbase + (rr - 16)) * 256 + cc];
        }
    }
    __syncthreads();

    const float* pl0 = sl + ti * PW_STR;
    const float* pl1 = sl + (ti + 8) * PW_STR;
    const float* pr0 = sr + tj * PW_STR;
    const float* pr1 = sr + (tj + 16) * PW_STR;
    float a00 = 0.f, a01 = 0.f, a10 = 0.f, a11 = 0.f;
#pragma unroll 2
    for (int d = 0; d < 256; d += 4) {
        float4 L0 = *(const float4*)(pl0 + d);
        float4 L1 = *(const float4*)(pl1 + d);
        float4 R0 = *(const float4*)(pr0 + d);
        float4 R1 = *(const float4*)(pr1 + d);
        float4 U  = *(const float4*)(su + d);
        a00 = fmaf(U.x, rcpf(fmaf(L0.x, R0.x, 1.0f)) - 0.5f, a00);
        a01 = fmaf(U.x, rcpf(fmaf(L0.x, R1.x, 1.0f)) - 0.5f, a01);
        a10 = fmaf(U.x, rcpf(fmaf(L1.x, R0.x, 1.0f)) - 0.5f, a10);
        a11 = fmaf(U.x, rcpf(fmaf(L1.x, R1.x, 1.0f)) - 0.5f, a11);
        a00 = fmaf(U.y, rcpf(fmaf(L0.y, R0.y, 1.0f)) - 0.5f, a00);
        a01 = fmaf(U.y, rcpf(fmaf(L0.y, R1.y, 1.0f)) - 0.5f, a01);
        a10 = fmaf(U.y, rcpf(fmaf(L1.y, R0.y, 1.0f)) - 0.5f, a10);
        a11 = fmaf(U.y, rcpf(fmaf(L1.y, R1.y, 1.0f)) - 0.5f, a11);
        a00 = fmaf(U.z, rcpf(fmaf(L0.z, R0.z, 1.0f)) - 0.5f, a00);
        a01 = fmaf(U.z, rcpf(fmaf(L0.z, R1.z, 1.0f)) - 0.5f, a01);
        a10 = fmaf(U.z, rcpf(fmaf(L1.z, R0.z, 1.0f)) - 0.5f, a10);
        a11 = fmaf(U.z, rcpf(fmaf(L1.z, R1.z, 1.0f)) - 0.5f, a11);
        a00 = fmaf(U.w, rcpf(fmaf(L0.w, R0.w, 1.0f)) - 0.5f, a00);
        a01 = fmaf(U.w, rcpf(fmaf(L0.w, R1.w, 1.0f)) - 0.5f, a01);
        a10 = fmaf(U.w, rcpf(fmaf(L1.w, R0.w, 1.0f)) - 0.5f, a10);
        a11 = fmaf(U.w, rcpf(fmaf(L1.w, R1.w, 1.0f)) - 0.5f, a11);
    }

    const float bias = __ldg(biasp);
    float2 e00 = epi_one(b, ibase + ti,     jbase + tj,      fmaf(-2.f, a00, bias), out);
    float2 e01 = epi_one(b, ibase + ti,     jbase + tj + 16, fmaf(-2.f, a01, bias), out);
    float2 e10 = epi_one(b, ibase + ti + 8, jbase + tj,      fmaf(-2.f, a10, bias), out);
    float2 e11 = epi_one(b, ibase + ti + 8, jbase + tj + 16, fmaf(-2.f, a11, bias), out);

    // per-tile block reduce (shfl tree + 4-warp combine), deterministic
    float ent = (e00.x + e01.x) + (e10.x + e11.x);
    float lsm = (e00.y + e01.y) + (e10.y + e11.y);
#pragma unroll
    for (int o = 16; o > 0; o >>= 1) {
        ent += __shfl_xor_sync(0xffffffffu, ent, o);
        lsm += __shfl_xor_sync(0xffffffffu, lsm, o);
    }
    if (lane == 0) { rshare[0][wid] = ent; rshare[1][wid] = lsm; }
    __syncthreads();
    const int t = (b * 8 + blockIdx.y) * 4 + blockIdx.x;   // 0..511, b-major
    if (tid == 0) {
        float se = 0.f, sm = 0.f;
#pragma unroll
        for (int ww = 0; ww < 4; ww++) { se += rshare[0][ww]; sm += rshare[1][ww]; }
        g_ent_part[t] = se;
        g_lsm_part[t] = sm;
    }

    // ---- fused tail: last finishing block ----
    if (tid == 0) {
        __threadfence();
        int d = atomicAdd(&g_done, 1);
        s_last = (d == (int)gridDim.x * (int)gridDim.y * (int)gridDim.z - 1) ? 1 : 0;
    }
    __syncthreads();
    if (s_last) {
        __threadfence();
        for (int k = tid; k < LL * LL; k += 128) {
            out[OFF_GB + k] = (float)g_cnt[k] * 0.0625f;
            g_cnt[k] = 0;
        }
        if (tid < 16) {   // entropy_reg: 32 tile-partials per batch, in order
            float s = 0.0f;
#pragma unroll
            for (int k = 0; k < 32; k++) s += g_ent_part[tid * 32 + k];
            out[OFF_ER + tid] = s * (1.0f / 16384.0f);
        }
        if (tid >= 32 && tid < 64) {   // log_softmax: 512 partials
            int ln = tid - 32;
            float s = 0.0f;
#pragma unroll
            for (int k = 0; k < 16; k++) s += g_lsm_part[ln * 16 + k];
#pragma unroll
            for (int o = 16; o > 0; o >>= 1)
                s += __shfl_xor_sync(0xffffffffu, s, o);
            if (ln == 0) out[OFF_LSM] = s * (1.0f / (float)NEL);
        }
        if (tid == 64) g_done = 0;     // reset for graph replay
    }
}

// ---------------------------------------------------------------------------
extern "C" void kernel_launch(void* const* d_in, const int* in_sizes, int n_in,
                              void* d_out, int out_size) {
    (void)in_sizes; (void)n_in; (void)out_size;
    const float* enc  = (const float*)d_in[0]; // (16,128,256)
    const float* W_l  = (const float*)d_in[1]; // (256,256)
    const float* W_r  = (const float*)d_in[2]; // (256,256)
    const float* U    = (const float*)d_in[3]; // (256,)
    const float* bias = (const float*)d_in[4]; // (1,)
    float* out = (float*)d_out;

    gemm_tc_kernel<<<dim3(4, 16, 2), 256>>>(enc, W_l, W_r);
    pairwise_kernel<<<dim3(4, 8, 16), 128>>>(U, bias, out);
}